// round 2
// baseline (speedup 1.0000x reference)
#include <cuda_runtime.h>
#include <cstdint>
#include <cstddef>

// ---------------- problem constants ----------------
#define Bn   4
#define Cc   128
#define Hh   128
#define Wd   256
#define HW   (Hh*Wd)          // 32768
#define Ff   128
#define CVC  49
#define RAD  24
#define NPIX (Bn*HW)          // 131072
static const size_t NC_ = (size_t)Bn * CVC * HW;  // 6,422,528 elements per corr-like tensor

// ---------------- device scratch (static, no allocation) ----------------
__device__ float g_f1n[(size_t)NPIX * Ff];   // 64 MB, normalized fmap1, [pixel][o]
__device__ float g_f2n[(size_t)NPIX * Ff];   // 64 MB, normalized fmap2, [pixel][o]
__device__ float g_Wt1[Cc * Ff];             // W_f1 transposed: [c][o]
__device__ float g_Wt2[Cc * Ff];
__device__ float g_M[9 * CVC];               // M[i][j][c] = sum_m W_sel[j, i*96+m] * W_geo[m,c]
__device__ float g_beta[3];                  // folded bias for logits

// ---------------- prep: transpose weights + fold selector ----------------
__global__ void prep_kernel(const float* __restrict__ Wf1, const float* __restrict__ Wf2,
                            const float* __restrict__ Wgeo, const float* __restrict__ bgeo,
                            const float* __restrict__ Wsel, const float* __restrict__ bsel)
{
    int t = threadIdx.x;
    for (int idx = t; idx < Cc * Ff; idx += blockDim.x) {
        int o = idx / Cc, c = idx % Cc;          // W layout [o][c]
        g_Wt1[c * Ff + o] = Wf1[idx];
        g_Wt2[c * Ff + o] = Wf2[idx];
    }
    for (int idx = t; idx < 9 * CVC; idx += blockDim.x) {
        int i = idx / (3 * CVC);
        int r = idx % (3 * CVC);
        int j = r / CVC;
        int c = r % CVC;
        float s = 0.f;
        for (int m = 0; m < 96; m++)
            s += Wsel[j * 288 + i * 96 + m] * Wgeo[m * CVC + c];
        g_M[idx] = s;
    }
    if (t < 3) {
        float s = bsel[t];
        for (int q = 0; q < 288; q++)
            s += Wsel[t * 288 + q] * bgeo[q % 96];
        g_beta[t] = s;
    }
}

// ---------------- fmap: conv1x1 (GEMM) + channel L2-normalize ----------------
// tile: 64 pixels x 128 outputs, 256 threads.
// thread micro-tile: 4 pixels x 8 outputs, packed f32x2 accumulators (FFMA2).
#define FM_PX 64
#define FM_KK 32

__global__ __launch_bounds__(256) void fmap_kernel(const float* __restrict__ feat,
                                                   const float* __restrict__ bias,
                                                   int which)
{
    __shared__ float featS[FM_KK][FM_PX];   // 8 KB
    __shared__ float wS[FM_KK][Ff];         // 16 KB
    __shared__ float ssS[FM_PX];

    const float* Wt   = which ? g_Wt2 : g_Wt1;
    float*       outp = which ? g_f2n : g_f1n;

    int t   = threadIdx.x;
    int p0  = blockIdx.x * FM_PX;
    int b   = p0 / HW;
    int rem = p0 % HW;
    const float* fbase = feat + (size_t)b * Cc * HW + rem;

    int o0  = (t & 15) * 8;   // output base (coalesced writes)
    int px0 = (t >> 4) * 4;   // pixel base

    unsigned long long acc[4][4];
    #pragma unroll
    for (int i = 0; i < 4; i++)
        #pragma unroll
        for (int j = 0; j < 4; j++) acc[i][j] = 0ULL;

    for (int c0 = 0; c0 < Cc; c0 += FM_KK) {
        __syncthreads();
        #pragma unroll
        for (int i = 0; i < 8; i++) {                 // 32*64 / 256
            int idx = t + i * 256;
            int c = idx >> 6, px = idx & 63;
            featS[c][px] = fbase[(size_t)(c0 + c) * HW + px];
        }
        #pragma unroll
        for (int i = 0; i < 16; i++) {                // 32*128 / 256
            int idx = t + i * 256;
            int c = idx >> 7, o = idx & 127;
            wS[c][o] = Wt[(c0 + c) * Ff + o];
        }
        __syncthreads();

        #pragma unroll
        for (int kk = 0; kk < FM_KK; kk++) {
            float4 a   = *(const float4*)&featS[kk][px0];
            float4 wv0 = *(const float4*)&wS[kk][o0];
            float4 wv1 = *(const float4*)&wS[kk][o0 + 4];
            unsigned long long w01, w23, w45, w67;
            asm("mov.b64 %0, {%1,%2};" : "=l"(w01) : "f"(wv0.x), "f"(wv0.y));
            asm("mov.b64 %0, {%1,%2};" : "=l"(w23) : "f"(wv0.z), "f"(wv0.w));
            asm("mov.b64 %0, {%1,%2};" : "=l"(w45) : "f"(wv1.x), "f"(wv1.y));
            asm("mov.b64 %0, {%1,%2};" : "=l"(w67) : "f"(wv1.z), "f"(wv1.w));
            float av[4] = {a.x, a.y, a.z, a.w};
            #pragma unroll
            for (int i = 0; i < 4; i++) {
                unsigned long long aa;
                asm("mov.b64 %0, {%1,%1};" : "=l"(aa) : "f"(av[i]));
                asm("fma.rn.f32x2 %0, %1, %2, %0;" : "+l"(acc[i][0]) : "l"(aa), "l"(w01));
                asm("fma.rn.f32x2 %0, %1, %2, %0;" : "+l"(acc[i][1]) : "l"(aa), "l"(w23));
                asm("fma.rn.f32x2 %0, %1, %2, %0;" : "+l"(acc[i][2]) : "l"(aa), "l"(w45));
                asm("fma.rn.f32x2 %0, %1, %2, %0;" : "+l"(acc[i][3]) : "l"(aa), "l"(w67));
            }
        }
    }

    // bias + unpack
    float bia[8];
    #pragma unroll
    for (int j = 0; j < 8; j++) bia[j] = bias[o0 + j];

    float v[4][8];
    #pragma unroll
    for (int i = 0; i < 4; i++)
        #pragma unroll
        for (int j2 = 0; j2 < 4; j2++) {
            float lo, hi;
            asm("mov.b64 {%0,%1}, %2;" : "=f"(lo), "=f"(hi) : "l"(acc[i][j2]));
            v[i][2 * j2]     = lo + bia[2 * j2];
            v[i][2 * j2 + 1] = hi + bia[2 * j2 + 1];
        }

    // per-pixel sum of squares (reduce across the 16 o-threads of each pixel)
    if (t < FM_PX) ssS[t] = 0.f;
    __syncthreads();
    #pragma unroll
    for (int i = 0; i < 4; i++) {
        float ss = 0.f;
        #pragma unroll
        for (int j = 0; j < 8; j++) ss += v[i][j] * v[i][j];
        atomicAdd(&ssS[px0 + i], ss);
    }
    __syncthreads();

    #pragma unroll
    for (int i = 0; i < 4; i++) {
        float inv = 1.f / (sqrtf(ssS[px0 + i]) + 1e-8f);
        float* op = outp + (size_t)(p0 + px0 + i) * Ff + o0;
        float4 s0 = make_float4(v[i][0] * inv, v[i][1] * inv, v[i][2] * inv, v[i][3] * inv);
        float4 s1 = make_float4(v[i][4] * inv, v[i][5] * inv, v[i][6] * inv, v[i][7] * inv);
        *(float4*)op       = s0;
        *(float4*)(op + 4) = s1;
    }
}

// ---------------- correlation volume ----------------
// block: one (b,h) row segment of 64 pixels; 224 threads = 7 warps.
// thread: 2 pixels (lx, lx+32) x 7 displacements; dot over 128 channels (float4).
#define CT_X   64
#define PROW   132        // padded row (floats), 16B-aligned rows
#define S2ROWS 112        // 64 + 2*24

extern __shared__ float csm[];
__global__ __launch_bounds__(224) void corr_kernel(float* __restrict__ out_corr)
{
    float* s1 = csm;                       // 64  x 132
    float* s2 = csm + CT_X * PROW;         // 112 x 132

    int t   = threadIdx.x;
    int blk = blockIdx.x;
    int bh  = blk >> 2;                    // b*H + h
    int x0  = (blk & 3) * CT_X;
    int b   = bh / Hh, h = bh % Hh;

    const float* base1 = g_f1n + ((size_t)bh * Wd + x0) * Ff;
    const float* base2 = g_f2n + (size_t)bh * Wd * Ff;

    for (int idx = t; idx < CT_X * (Ff / 4); idx += 224) {
        int px = idx >> 5, o4 = idx & 31;
        *(float4*)&s1[px * PROW + o4 * 4] = *(const float4*)&base1[(size_t)px * Ff + o4 * 4];
    }
    for (int idx = t; idx < S2ROWS * (Ff / 4); idx += 224) {
        int r = idx >> 5, o4 = idx & 31;
        int xg = x0 - RAD + r;             // s2 row r  <->  global x' = x0 - 24 + r
        float4 vv = make_float4(0.f, 0.f, 0.f, 0.f);
        if (xg >= 0 && xg < Wd) vv = *(const float4*)&base2[(size_t)xg * Ff + o4 * 4];
        *(float4*)&s2[r * PROW + o4 * 4] = vv;
    }
    __syncthreads();

    int kg = t >> 5;       // 0..6
    int lx = t & 31;       // 0..31
    int k0 = kg * 7;

    float4 acc[2][7];
    #pragma unroll
    for (int i = 0; i < 2; i++)
        #pragma unroll
        for (int kk = 0; kk < 7; kk++) acc[i][kk] = make_float4(0.f, 0.f, 0.f, 0.f);

    for (int o = 0; o < Ff; o += 4) {
        float4 a0 = *(const float4*)&s1[lx * PROW + o];
        float4 a1 = *(const float4*)&s1[(lx + 32) * PROW + o];
        #pragma unroll
        for (int kk = 0; kk < 7; kk++) {
            // out[k][x] = sum_o f1n[x][o] * f2n[x + 24 - k][o];  s2 row = xl + 48 - k
            int r = lx + 48 - (k0 + kk);
            float4 b0 = *(const float4*)&s2[r * PROW + o];
            float4 b1 = *(const float4*)&s2[(r + 32) * PROW + o];
            acc[0][kk].x = fmaf(a0.x, b0.x, acc[0][kk].x);
            acc[0][kk].y = fmaf(a0.y, b0.y, acc[0][kk].y);
            acc[0][kk].z = fmaf(a0.z, b0.z, acc[0][kk].z);
            acc[0][kk].w = fmaf(a0.w, b0.w, acc[0][kk].w);
            acc[1][kk].x = fmaf(a1.x, b1.x, acc[1][kk].x);
            acc[1][kk].y = fmaf(a1.y, b1.y, acc[1][kk].y);
            acc[1][kk].z = fmaf(a1.z, b1.z, acc[1][kk].z);
            acc[1][kk].w = fmaf(a1.w, b1.w, acc[1][kk].w);
        }
    }

    #pragma unroll
    for (int kk = 0; kk < 7; kk++) {
        int k = k0 + kk;
        float v0 = (acc[0][kk].x + acc[0][kk].y) + (acc[0][kk].z + acc[0][kk].w);
        float v1 = (acc[1][kk].x + acc[1][kk].y) + (acc[1][kk].z + acc[1][kk].w);
        size_t obase = ((size_t)(b * CVC + k) * Hh + h) * Wd + x0;
        out_corr[obase + lx]      = v0;
        out_corr[obase + lx + 32] = v1;
    }
}

// ---------------- selector: folded logits + softmax + weighted sum + final ----------------
__global__ __launch_bounds__(256) void select_kernel(const float* __restrict__ cv0,
                                                     const float* __restrict__ cv1,
                                                     const float* __restrict__ cv2,
                                                     float* __restrict__ out)
{
    __shared__ float Ms[9 * CVC];
    __shared__ float betaS[3];
    int t = threadIdx.x;
    for (int i = t; i < 9 * CVC; i += 256) Ms[i] = g_M[i];
    if (t < 3) betaS[t] = g_beta[t];
    __syncthreads();

    int p = blockIdx.x * 256 + t;
    int b = p / HW, rem = p % HW;
    size_t base = (size_t)b * CVC * HW + rem;
    const float* p0 = cv0 + base;
    const float* p1 = cv1 + base;
    const float* p2 = cv2 + base;

    float l0 = betaS[0], l1 = betaS[1], l2 = betaS[2];
    #pragma unroll 7
    for (int c = 0; c < CVC; c++) {
        size_t off = (size_t)c * HW;
        float v0 = p0[off], v1 = p1[off], v2 = p2[off];
        l0 = fmaf(Ms[0 * CVC + c], v0, fmaf(Ms[147 + 0 * CVC + c], v1, fmaf(Ms[294 + 0 * CVC + c], v2, l0)));
        l1 = fmaf(Ms[1 * CVC + c], v0, fmaf(Ms[147 + 1 * CVC + c], v1, fmaf(Ms[294 + 1 * CVC + c], v2, l1)));
        l2 = fmaf(Ms[2 * CVC + c], v0, fmaf(Ms[147 + 2 * CVC + c], v1, fmaf(Ms[294 + 2 * CVC + c], v2, l2)));
    }

    float m  = fmaxf(l0, fmaxf(l1, l2));
    float e0 = expf(l0 - m), e1 = expf(l1 - m), e2 = expf(l2 - m);
    float inv = 1.f / (e0 + e1 + e2);
    float w0 = e0 * inv, w1 = e1 * inv, w2 = e2 * inv;

    const float* corr = out + NC_ + base;   // init_corr region (already written)
    float* fin = out + base;                // final region
    #pragma unroll 7
    for (int c = 0; c < CVC; c++) {
        size_t off = (size_t)c * HW;
        fin[off] = corr[off] + fmaf(w0, p0[off], fmaf(w1, p1[off], w2 * p2[off]));
    }

    float* wout = out + 2 * NC_;
    size_t wbase = (size_t)b * 3 * HW + rem;
    wout[wbase]           = w0;
    wout[wbase + HW]      = w1;
    wout[wbase + 2 * HW]  = w2;
}

// ---------------- launch ----------------
extern "C" void kernel_launch(void* const* d_in, const int* in_sizes, int n_in,
                              void* d_out, int out_size)
{
    const float* feat_l1 = (const float*)d_in[0];
    const float* feat_r1 = (const float*)d_in[1];
    const float* cv0     = (const float*)d_in[2];
    const float* cv1     = (const float*)d_in[3];
    const float* cv2     = (const float*)d_in[4];
    const float* W_f1    = (const float*)d_in[5];
    const float* b_f1    = (const float*)d_in[6];
    const float* W_f2    = (const float*)d_in[7];
    const float* b_f2    = (const float*)d_in[8];
    const float* W_geo   = (const float*)d_in[9];
    const float* b_geo   = (const float*)d_in[10];
    const float* W_sel   = (const float*)d_in[11];
    const float* b_sel   = (const float*)d_in[12];
    float* out = (float*)d_out;

    prep_kernel<<<1, 256>>>(W_f1, W_f2, W_geo, b_geo, W_sel, b_sel);

    fmap_kernel<<<NPIX / FM_PX, 256>>>(feat_l1, b_f1, 0);
    fmap_kernel<<<NPIX / FM_PX, 256>>>(feat_r1, b_f2, 1);

    int smem = (CT_X + S2ROWS) * PROW * (int)sizeof(float);   // 92,928 B
    cudaFuncSetAttribute(corr_kernel, cudaFuncAttributeMaxDynamicSharedMemorySize, smem);
    corr_kernel<<<Bn * Hh * (Wd / CT_X), 224, smem>>>(out + NC_);

    select_kernel<<<NPIX / 256, 256>>>(cv0, cv1, cv2, out);
}

// round 3
// speedup vs baseline: 1.6649x; 1.6649x over previous
#include <cuda_runtime.h>
#include <cstdint>
#include <cstddef>

// ---------------- problem constants ----------------
#define Bn   4
#define Cc   128
#define Hh   128
#define Wd   256
#define HW   (Hh*Wd)          // 32768
#define Ff   128
#define CVC  49
#define RAD  24
#define NPIX (Bn*HW)          // 131072
static const size_t NC_ = (size_t)Bn * CVC * HW;  // elements per corr-like tensor

// ---------------- device scratch (static, no allocation) ----------------
// fmaps stored channel-major [B][F][H][W] (same layout as conv output)
__device__ float g_f1n[(size_t)NPIX * Ff];
__device__ float g_f2n[(size_t)NPIX * Ff];
__device__ float g_Wt1[Cc * Ff];             // W transposed: [c][o]
__device__ float g_Wt2[Cc * Ff];
__device__ float g_M[9 * CVC];
__device__ float g_beta[3];

// ---------------- f32x2 helpers ----------------
__device__ __forceinline__ unsigned long long bcast2(float v) {
    unsigned long long r; asm("mov.b64 %0, {%1,%1};" : "=l"(r) : "f"(v)); return r;
}
__device__ __forceinline__ void unpack2(unsigned long long p, float& lo, float& hi) {
    asm("mov.b64 {%0,%1}, %2;" : "=f"(lo), "=f"(hi) : "l"(p));
}
__device__ __forceinline__ void ffma2(unsigned long long& acc, unsigned long long a, unsigned long long b) {
    asm("fma.rn.f32x2 %0, %1, %2, %0;" : "+l"(acc) : "l"(a), "l"(b));
}

// ---------------- prep: transpose weights + fold selector ----------------
__global__ void prep_kernel(const float* __restrict__ Wf1, const float* __restrict__ Wf2,
                            const float* __restrict__ Wgeo, const float* __restrict__ bgeo,
                            const float* __restrict__ Wsel, const float* __restrict__ bsel)
{
    int t = threadIdx.x;
    for (int idx = t; idx < Cc * Ff; idx += blockDim.x) {
        int o = idx / Cc, c = idx % Cc;          // W layout [o][c]
        g_Wt1[c * Ff + o] = Wf1[idx];
        g_Wt2[c * Ff + o] = Wf2[idx];
    }
    for (int idx = t; idx < 9 * CVC; idx += blockDim.x) {
        int i = idx / (3 * CVC);
        int r = idx % (3 * CVC);
        int j = r / CVC;
        int c = r % CVC;
        float s = 0.f;
        for (int m = 0; m < 96; m++)
            s += Wsel[j * 288 + i * 96 + m] * Wgeo[m * CVC + c];
        g_M[idx] = s;
    }
    if (t < 3) {
        float s = bsel[t];
        for (int q = 0; q < 288; q++)
            s += Wsel[t * 288 + q] * bgeo[q % 96];
        g_beta[t] = s;
    }
}

// ---------------- fmap: conv1x1 (GEMM) + channel L2-normalize ----------------
// tile: 128 px x 128 outputs, K-tiles of 32, 256 threads.
// thread micro-tile: 8 outputs x 8 pixels; f32x2 accumulators paired over pixels
// (feat pairs load directly as u64 from smem -> no packing movs for feat;
//  only 8 broadcast packs per 32 FFMA2).
#define FMP 128
#define FMK 32

__global__ __launch_bounds__(256) void fmap_kernel(
    const float* __restrict__ featA, const float* __restrict__ featB,
    const float* __restrict__ biasA, const float* __restrict__ biasB)
{
    __shared__ float featS[FMK][132];   // padded rows
    __shared__ float wS[FMK][Ff];
    __shared__ float ssS[FMP];

    int which = blockIdx.y;
    const float* feat = which ? featB : featA;
    const float* bias = which ? biasB : biasA;
    const float* Wt   = which ? g_Wt2 : g_Wt1;
    float*       outp = which ? g_f2n : g_f1n;

    int t   = threadIdx.x;
    int p0  = blockIdx.x * FMP;
    int b   = p0 / HW;
    int rem = p0 % HW;                  // 128-aligned within a row (W=256)
    const float* fbase = feat + (size_t)b * Cc * HW + rem;

    int pg  = t & 15,  og = t >> 4;
    int px0 = pg * 8,  o0 = og * 8;     // lanes 0..15 cover px 0..127 -> coalesced stores

    if (t < FMP) ssS[t] = 0.f;

    unsigned long long acc[8][4];
    #pragma unroll
    for (int i = 0; i < 8; i++)
        #pragma unroll
        for (int j = 0; j < 4; j++) acc[i][j] = 0ULL;

    for (int c0 = 0; c0 < Cc; c0 += FMK) {
        __syncthreads();
        #pragma unroll
        for (int it = 0; it < 4; it++) {                  // 32*32 float4 = 1024
            int idx = t + it * 256;
            int kc = idx >> 5, q = idx & 31;
            *(float4*)&featS[kc][q * 4] =
                *(const float4*)&fbase[(size_t)(c0 + kc) * HW + q * 4];
        }
        #pragma unroll
        for (int it = 0; it < 4; it++) {
            int idx = t + it * 256;
            int kc = idx >> 5, q = idx & 31;
            *(float4*)&wS[kc][q * 4] = *(const float4*)&Wt[(c0 + kc) * Ff + q * 4];
        }
        __syncthreads();

        #pragma unroll
        for (int kk = 0; kk < FMK; kk++) {
            ulonglong2 f01 = *(const ulonglong2*)&featS[kk][px0];      // px pairs 0,1
            ulonglong2 f23 = *(const ulonglong2*)&featS[kk][px0 + 4];  // px pairs 2,3
            float4 w0 = *(const float4*)&wS[kk][o0];
            float4 w1 = *(const float4*)&wS[kk][o0 + 4];
            float wv[8] = {w0.x, w0.y, w0.z, w0.w, w1.x, w1.y, w1.z, w1.w};
            #pragma unroll
            for (int oi = 0; oi < 8; oi++) {
                unsigned long long ww = bcast2(wv[oi]);
                ffma2(acc[oi][0], ww, f01.x);
                ffma2(acc[oi][1], ww, f01.y);
                ffma2(acc[oi][2], ww, f23.x);
                ffma2(acc[oi][3], ww, f23.y);
            }
        }
    }

    float bia[8];
    #pragma unroll
    for (int oi = 0; oi < 8; oi++) bia[oi] = bias[o0 + oi];

    // pass 1: per-pixel sums of squares (unpack on the fly, acc stays packed)
    float ss[8];
    #pragma unroll
    for (int pp = 0; pp < 8; pp++) ss[pp] = 0.f;
    #pragma unroll
    for (int oi = 0; oi < 8; oi++)
        #pragma unroll
        for (int p = 0; p < 4; p++) {
            float lo, hi; unpack2(acc[oi][p], lo, hi);
            lo += bia[oi]; hi += bia[oi];
            ss[2 * p]     += lo * lo;
            ss[2 * p + 1] += hi * hi;
        }
    #pragma unroll
    for (int pp = 0; pp < 8; pp++) atomicAdd(&ssS[px0 + pp], ss[pp]);
    __syncthreads();

    float inv[8];
    #pragma unroll
    for (int pp = 0; pp < 8; pp++) inv[pp] = 1.f / (sqrtf(ssS[px0 + pp]) + 1e-8f);

    // pass 2: scale + coalesced stores (512B rows across lanes 0..15)
    #pragma unroll
    for (int oi = 0; oi < 8; oi++) {
        float v[8];
        #pragma unroll
        for (int p = 0; p < 4; p++) {
            float lo, hi; unpack2(acc[oi][p], lo, hi);
            v[2 * p]     = (lo + bia[oi]) * inv[2 * p];
            v[2 * p + 1] = (hi + bia[oi]) * inv[2 * p + 1];
        }
        float* op = outp + ((size_t)b * Ff + o0 + oi) * HW + rem + px0;
        *(float4*)op       = make_float4(v[0], v[1], v[2], v[3]);
        *(float4*)(op + 4) = make_float4(v[4], v[5], v[6], v[7]);
    }
}

// ---------------- correlation volume ----------------
// block: 64 x-positions of one (b,h) row, all 49 displacements.
// banded Gram matrix with rectangular 4x4 (x, x') register tiles:
//   thread (xt, j), xt in [0,16), j in [0,13):
//     a rows: x_local = 4*xt + i           (i 0..3)
//     b rows: r       = 4*(xt+j) + i'      (i' 0..3), r = local x' index
//     k = 48 - 4*j + i - i'   (store iff 0<=k<=48; only j=0/12 partial)
// channel-major smem tiles (s[ch][x]) -> all LDS contiguous, b pairs load as u64.
// channels processed in 2 halves of 64 -> 46KB smem -> 4 blocks/SM (occ 44%).
__global__ __launch_bounds__(224) void corr_kernel(float* __restrict__ out_corr)
{
    __shared__ float s1c[64 * 68];     // 64 ch x (64 x + pad)
    __shared__ float s2c[64 * 116];    // 64 ch x (112 x' + pad)
    float* outS = s1c;                 // reused for staged stores (49*64 <= 64*68)

    int t   = threadIdx.x;
    int blk = blockIdx.x;
    int bh  = blk >> 2;
    int x0  = (blk & 3) * 64;
    int b   = bh / Hh, h = bh % Hh;

    const float* f1 = g_f1n + (size_t)b * Ff * HW + (size_t)h * Wd;  // + c*HW + x
    const float* f2 = g_f2n + (size_t)b * Ff * HW + (size_t)h * Wd;

    int xt = t & 15, j = t >> 4;       // j 0..13 (j==13 -> load-only helper)
    bool active = (j < 13);

    unsigned long long acc[4][2];
    #pragma unroll
    for (int i = 0; i < 4; i++) { acc[i][0] = 0ULL; acc[i][1] = 0ULL; }

    for (int half = 0; half < 2; half++) {
        __syncthreads();
        int cbase = half * 64;
        for (int idx = t; idx < 1024; idx += 224) {        // 64 ch x 16 float4
            int o = idx >> 4, q = idx & 15;
            *(float4*)&s1c[o * 68 + q * 4] =
                *(const float4*)&f1[(size_t)(cbase + o) * HW + x0 + q * 4];
        }
        for (int idx = t; idx < 1792; idx += 224) {        // 64 ch x 28 float4
            int o = idx / 28, q = idx - o * 28;
            int xg = x0 - RAD + q * 4;                     // OOB always whole-float4
            float4 vv = make_float4(0.f, 0.f, 0.f, 0.f);
            if (xg >= 0 && xg <= Wd - 4)
                vv = *(const float4*)&f2[(size_t)(cbase + o) * HW + xg];
            *(float4*)&s2c[o * 116 + q * 4] = vv;
        }
        __syncthreads();

        if (active) {
            #pragma unroll 4
            for (int o = 0; o < 64; o++) {
                float4 a = *(const float4*)&s1c[o * 68 + 4 * xt];
                ulonglong2 bb = *(const ulonglong2*)&s2c[o * 116 + 4 * (xt + j)];
                float av[4] = {a.x, a.y, a.z, a.w};
                #pragma unroll
                for (int i = 0; i < 4; i++) {
                    unsigned long long aa = bcast2(av[i]);
                    ffma2(acc[i][0], aa, bb.x);
                    ffma2(acc[i][1], aa, bb.y);
                }
            }
        }
    }

    __syncthreads();                   // all reads of s1c done before outS reuse
    if (active) {
        #pragma unroll
        for (int i = 0; i < 4; i++) {
            float vals[4];
            unpack2(acc[i][0], vals[0], vals[1]);
            unpack2(acc[i][1], vals[2], vals[3]);
            #pragma unroll
            for (int ip = 0; ip < 4; ip++) {
                int k = 48 - 4 * j + i - ip;
                if (k >= 0 && k <= 48)
                    outS[k * 64 + 4 * xt + i] = vals[ip];
            }
        }
    }
    __syncthreads();
    for (int idx = t; idx < 784; idx += 224) {             // 49 k x 16 float4
        int k = idx >> 4, q = idx & 15;
        *(float4*)&out_corr[((size_t)(b * CVC + k) * Hh + h) * Wd + x0 + q * 4] =
            *(const float4*)&outS[k * 64 + q * 4];
    }
}

// ---------------- selector: folded logits + softmax + weighted sum + final ----------------
__global__ __launch_bounds__(256) void select_kernel(const float* __restrict__ cv0,
                                                     const float* __restrict__ cv1,
                                                     const float* __restrict__ cv2,
                                                     float* __restrict__ out)
{
    __shared__ float Ms[9 * CVC];
    __shared__ float betaS[3];
    int t = threadIdx.x;
    for (int i = t; i < 9 * CVC; i += 256) Ms[i] = g_M[i];
    if (t < 3) betaS[t] = g_beta[t];
    __syncthreads();

    int p = blockIdx.x * 256 + t;
    int b = p / HW, rem = p % HW;
    size_t base = (size_t)b * CVC * HW + rem;
    const float* p0 = cv0 + base;
    const float* p1 = cv1 + base;
    const float* p2 = cv2 + base;

    float l0 = betaS[0], l1 = betaS[1], l2 = betaS[2];
    #pragma unroll 7
    for (int c = 0; c < CVC; c++) {
        size_t off = (size_t)c * HW;
        float v0 = p0[off], v1 = p1[off], v2 = p2[off];
        l0 = fmaf(Ms[0 * CVC + c], v0, fmaf(Ms[147 + 0 * CVC + c], v1, fmaf(Ms[294 + 0 * CVC + c], v2, l0)));
        l1 = fmaf(Ms[1 * CVC + c], v0, fmaf(Ms[147 + 1 * CVC + c], v1, fmaf(Ms[294 + 1 * CVC + c], v2, l1)));
        l2 = fmaf(Ms[2 * CVC + c], v0, fmaf(Ms[147 + 2 * CVC + c], v1, fmaf(Ms[294 + 2 * CVC + c], v2, l2)));
    }

    float m  = fmaxf(l0, fmaxf(l1, l2));
    float e0 = expf(l0 - m), e1 = expf(l1 - m), e2 = expf(l2 - m);
    float inv = 1.f / (e0 + e1 + e2);
    float w0 = e0 * inv, w1 = e1 * inv, w2 = e2 * inv;

    const float* corr = out + NC_ + base;   // init_corr region (already written)
    float* fin = out + base;                // final region
    #pragma unroll 7
    for (int c = 0; c < CVC; c++) {
        size_t off = (size_t)c * HW;
        fin[off] = corr[off] + fmaf(w0, p0[off], fmaf(w1, p1[off], w2 * p2[off]));
    }

    float* wout = out + 2 * NC_;
    size_t wbase = (size_t)b * 3 * HW + rem;
    wout[wbase]           = w0;
    wout[wbase + HW]      = w1;
    wout[wbase + 2 * HW]  = w2;
}

// ---------------- launch ----------------
extern "C" void kernel_launch(void* const* d_in, const int* in_sizes, int n_in,
                              void* d_out, int out_size)
{
    const float* feat_l1 = (const float*)d_in[0];
    const float* feat_r1 = (const float*)d_in[1];
    const float* cv0     = (const float*)d_in[2];
    const float* cv1     = (const float*)d_in[3];
    const float* cv2     = (const float*)d_in[4];
    const float* W_f1    = (const float*)d_in[5];
    const float* b_f1    = (const float*)d_in[6];
    const float* W_f2    = (const float*)d_in[7];
    const float* b_f2    = (const float*)d_in[8];
    const float* W_geo   = (const float*)d_in[9];
    const float* b_geo   = (const float*)d_in[10];
    const float* W_sel   = (const float*)d_in[11];
    const float* b_sel   = (const float*)d_in[12];
    float* out = (float*)d_out;

    prep_kernel<<<1, 256>>>(W_f1, W_f2, W_geo, b_geo, W_sel, b_sel);

    fmap_kernel<<<dim3(NPIX / FMP, 2), 256>>>(feat_l1, feat_r1, b_f1, b_f2);

    corr_kernel<<<Bn * Hh * (Wd / 64), 224>>>(out + NC_);

    select_kernel<<<NPIX / 256, 256>>>(cv0, cv1, cv2, out);
}